// round 3
// baseline (speedup 1.0000x reference)
#include <cuda_runtime.h>
#include <cstdint>

// UpsampleLayer2D quadrant depth-to-space:
// out[b, r2, c2, co] = x[b, r2%R, c2%C, 4*co + k],  k = 2*(r2>=R) + (c2>=C)
// B=32, R=C=200, Cin=64, Co=16.
//
// R2: 2 pixels per thread, 8 front-batched LDG.128 (MLP=8) + 8 STG.128.
// Goal: keep DRAM read queues fuller (DRAM was 83.8% with issue at 9%).
// Warp reads 4KB contiguous; per quadrant a warp writes 1KB contiguous.

static constexpr int B  = 32;
static constexpr int R  = 200;
static constexpr int C  = 200;
static constexpr int CO = 16;                       // output channels
static constexpr unsigned PIX = B * R * C;          // 1,280,000 pixels
static constexpr unsigned NTHREADS = PIX * 4 / 2;   // 2,560,000 = 5000 * 512

// float4 strides in the output [B, 2R, 2C, CO]:
static constexpr size_t OUT_ROW_F4  = (size_t)(2 * C) * CO / 4;   // 1600
static constexpr size_t Q_COL_OFF   = (size_t)C * CO / 4;         // 800
static constexpr size_t Q_ROW_OFF   = (size_t)R * OUT_ROW_F4;     // 320000

__device__ __forceinline__ size_t out_f4_index(unsigned pix, unsigned co4)
{
    unsigned c  = pix % (unsigned)C;
    unsigned rb = pix / (unsigned)C;
    unsigned r  = rb % (unsigned)R;
    unsigned b  = rb / (unsigned)R;
    size_t opix = ((size_t)b * (2 * R) + r) * (2 * C) + c;  // quadrant-0 pixel
    return opix * 4 + co4;
}

__global__ __launch_bounds__(512) void upsample2d_kernel(
    const float4* __restrict__ x4, float4* __restrict__ out4)
{
    unsigned g    = blockIdx.x * 512u + threadIdx.x;  // grid sized exactly
    unsigned co4  = g & 3u;            // group of 4 output channels
    unsigned pair = g >> 2;            // pair of consecutive input pixels
    unsigned pix0 = pair * 2u;
    unsigned pix1 = pix0 + 1u;

    const float4* s0 = x4 + (size_t)pix0 * 16 + (size_t)co4 * 4;
    const float4* s1 = x4 + (size_t)pix1 * 16 + (size_t)co4 * 4;

    // Front-batched loads: 8 independent LDG.128 in flight.
    float4 a0 = __ldcs(s0 + 0);
    float4 a1 = __ldcs(s0 + 1);
    float4 a2 = __ldcs(s0 + 2);
    float4 a3 = __ldcs(s0 + 3);
    float4 b0 = __ldcs(s1 + 0);
    float4 b1 = __ldcs(s1 + 1);
    float4 b2 = __ldcs(s1 + 2);
    float4 b3 = __ldcs(s1 + 3);

    size_t oA = out_f4_index(pix0, co4);
    size_t oB = out_f4_index(pix1, co4);

    __stcs(out4 + oA,                         make_float4(a0.x, a1.x, a2.x, a3.x)); // TL
    __stcs(out4 + oB,                         make_float4(b0.x, b1.x, b2.x, b3.x));
    __stcs(out4 + oA + Q_COL_OFF,             make_float4(a0.y, a1.y, a2.y, a3.y)); // TR
    __stcs(out4 + oB + Q_COL_OFF,             make_float4(b0.y, b1.y, b2.y, b3.y));
    __stcs(out4 + oA + Q_ROW_OFF,             make_float4(a0.z, a1.z, a2.z, a3.z)); // BL
    __stcs(out4 + oB + Q_ROW_OFF,             make_float4(b0.z, b1.z, b2.z, b3.z));
    __stcs(out4 + oA + Q_ROW_OFF + Q_COL_OFF, make_float4(a0.w, a1.w, a2.w, a3.w)); // BR
    __stcs(out4 + oB + Q_ROW_OFF + Q_COL_OFF, make_float4(b0.w, b1.w, b2.w, b3.w));
}

extern "C" void kernel_launch(void* const* d_in, const int* in_sizes, int n_in,
                              void* d_out, int out_size)
{
    const float4* x4   = (const float4*)d_in[0];
    float4*       out4 = (float4*)d_out;

    // NTHREADS = 2,560,000 = 5000 * 512 exactly; no bounds check needed.
    upsample2d_kernel<<<NTHREADS / 512, 512>>>(x4, out4);
}